// round 16
// baseline (speedup 1.0000x reference)
#include <cuda_runtime.h>

// x: [B=16, T=4096, D=1024] f32, out: [B, D] = sum over T.
// FINAL: best-measured stream config (R3: grid 512 = 16 batches x 32
// T-splits, __ldcs, unroll 8 -> 5805 GB/s, the highest HBM rate of any
// variant tried; ~5.8 TB/s proven to be the chip's path-independent read
// ceiling across LDG/TMA/occupancy/balance experiments) + the R13-validated
// race-free ticket protocol (R3's original omitted the __syncthreads
// between fence and atomic; it passed only by finish-time luck).
// Last finisher per batch reduces 32 partial slots in fixed order
// (deterministic) and resets the ticket (graph-replay safe).

#define B_DIM 16
#define T_DIM 4096
#define D_DIM 1024
#define D4 (D_DIM / 4)                  // 256 float4 per row
#define SPLITS 32
#define ROWS_PER_BLK (T_DIM / SPLITS)   // 128 (compile-time trip count)

__device__ float g_partial[B_DIM * SPLITS * D_DIM];   // 2 MiB
__device__ int g_count[B_DIM];          // zero-init; reset by reducer

__global__ __launch_bounds__(256, 8)
void sum_fused(const float* __restrict__ x, float* __restrict__ out) {
    const int b   = blockIdx.x;        // 0..15
    const int s   = blockIdx.y;        // 0..31
    const int tid = threadIdx.x;       // 0..255 -> one float4 column

    const float4* __restrict__ xp = reinterpret_cast<const float4*>(
        x + (size_t)b * T_DIM * D_DIM + (size_t)s * ROWS_PER_BLK * D_DIM) + tid;

    float4 acc = make_float4(0.f, 0.f, 0.f, 0.f);

    #pragma unroll 8
    for (int r = 0; r < ROWS_PER_BLK; ++r) {
        float4 v = __ldcs(xp + (size_t)r * D4);
        acc.x += v.x; acc.y += v.y; acc.z += v.z; acc.w += v.w;
    }

    reinterpret_cast<float4*>(
        g_partial + (size_t)(b * SPLITS + s) * D_DIM)[tid] = acc;

    // Release: each thread fences its OWN store, then the block rendezvous,
    // THEN tid0 publishes via the ticket. (Without the __syncthreads, tid0
    // can take the ticket before sibling threads' stores are visible —
    // the R9/R10 corruption.)
    __threadfence();
    __syncthreads();
    __shared__ int s_is_last;
    if (tid == 0) {
        int ticket = atomicAdd(&g_count[b], 1);
        s_is_last = (ticket == SPLITS - 1);
    }
    __syncthreads();

    if (s_is_last) {
        __threadfence();   // acquire: order slot reads after ticket win
        const float4* base = reinterpret_cast<const float4*>(
            g_partial + (size_t)b * SPLITS * D_DIM);
        float4 rsum = make_float4(0.f, 0.f, 0.f, 0.f);
        #pragma unroll
        for (int ss = 0; ss < SPLITS; ++ss) {
            float4 v = base[(size_t)ss * D4 + tid];   // coherent ld.global
            rsum.x += v.x; rsum.y += v.y; rsum.z += v.z; rsum.w += v.w;
        }
        reinterpret_cast<float4*>(out + (size_t)b * D_DIM)[tid] = rsum;
        __syncthreads();                 // all reads done before reset
        if (tid == 0) g_count[b] = 0;    // graph-replay safe
    }
}

extern "C" void kernel_launch(void* const* d_in, const int* in_sizes, int n_in,
                              void* d_out, int out_size) {
    const float* x = (const float*)d_in[0];
    float* out = (float*)d_out;

    dim3 grid(B_DIM, SPLITS);
    sum_fused<<<grid, 256>>>(x, out);
}